// round 1
// baseline (speedup 1.0000x reference)
#include <cuda_runtime.h>
#include <cuda_bf16.h>

#define N_NODES 8192
#define IN_F    128
#define HID     64
#define OUT_F   128
#define BM      64
#define BN      64

// K-row stride in smem: 64 data bf16 + 8 pad = 72 bf16 = 36 words = 9 uint4.
// Bank check: word addr = 36*n + j, lanes have n=lr (0..7), j=qi (0..3)
//  -> bank = (4n + j) mod 32 : all 32 distinct -> conflict-free.
#define KSTRW 36
#define KSTR4 9

// ---------------- scratch (static device globals; no allocs allowed) -----
__device__ __align__(16) __nv_bfloat16 g_Qh[N_NODES * HID];
__device__ __align__(16) __nv_bfloat16 g_Ql[N_NODES * HID];
__device__ __align__(16) __nv_bfloat16 g_Kh[N_NODES * HID];
__device__ __align__(16) __nv_bfloat16 g_Kl[N_NODES * HID];
// V stored TRANSPOSED: [OUT_F][N_NODES] so flash-kernel smem fills are coalesced
__device__ __align__(16) __nv_bfloat16 g_Vth[OUT_F * N_NODES];
__device__ __align__(16) __nv_bfloat16 g_Vtl[OUT_F * N_NODES];

// ---------------- prep: Whs/Wht/Whc + bf16 hi/lo splits ------------------
// grid 512 blocks x 256 threads; block handles 16 rows of h.
// thread t: t<64 -> Ws col t; 64<=t<128 -> Wt col t-64; t>=128 -> Wc col t-128.
__global__ void prep_kernel(const float* __restrict__ h,
                            const float* __restrict__ Ws,
                            const float* __restrict__ Wt,
                            const float* __restrict__ Wc) {
    __shared__ float hs[16][128];
    const int row0 = blockIdx.x * 16;
    const int tid  = threadIdx.x;

    for (int i = tid; i < 16 * 128; i += 256)
        hs[i >> 7][i & 127] = h[(row0 + (i >> 7)) * IN_F + (i & 127)];
    __syncthreads();

    const float* W;
    int stride, cc;
    if (tid < 64)       { W = Ws; stride = 64;  cc = tid; }
    else if (tid < 128) { W = Wt; stride = 64;  cc = tid - 64; }
    else                { W = Wc; stride = 128; cc = tid - 128; }

    float acc[16];
#pragma unroll
    for (int r = 0; r < 16; r++) acc[r] = 0.f;

#pragma unroll 4
    for (int k = 0; k < 128; k += 4) {
        float w0 = W[(k + 0) * stride + cc];
        float w1 = W[(k + 1) * stride + cc];
        float w2 = W[(k + 2) * stride + cc];
        float w3 = W[(k + 3) * stride + cc];
#pragma unroll
        for (int r = 0; r < 16; r++) {
            float4 hv = *(const float4*)&hs[r][k];
            acc[r] += hv.x * w0 + hv.y * w1 + hv.z * w2 + hv.w * w3;
        }
    }

    if (tid < 128) {
        __nv_bfloat16* dh = (tid < 64) ? g_Qh : g_Kh;
        __nv_bfloat16* dl = (tid < 64) ? g_Ql : g_Kl;
#pragma unroll
        for (int r = 0; r < 16; r++) {
            float v = acc[r];
            __nv_bfloat16 hi = __float2bfloat16(v);
            __nv_bfloat16 lo = __float2bfloat16(v - __bfloat162float(hi));
            dh[(row0 + r) * HID + cc] = hi;
            dl[(row0 + r) * HID + cc] = lo;
        }
    } else {
        union { __nv_bfloat16 b[8]; uint4 u; } h0, h1, l0, l1;
#pragma unroll
        for (int r = 0; r < 16; r++) {
            float v = acc[r];
            __nv_bfloat16 hi = __float2bfloat16(v);
            __nv_bfloat16 lo = __float2bfloat16(v - __bfloat162float(hi));
            if (r < 8) { h0.b[r] = hi; l0.b[r] = lo; }
            else       { h1.b[r - 8] = hi; l1.b[r - 8] = lo; }
        }
        size_t base = (size_t)cc * N_NODES + row0;  // 16 consecutive rows = 32B
        *(uint4*)(g_Vth + base)     = h0.u;
        *(uint4*)(g_Vth + base + 8) = h1.u;
        *(uint4*)(g_Vtl + base)     = l0.u;
        *(uint4*)(g_Vtl + base + 8) = l1.u;
    }
}

// ---------------- flash attention ----------------------------------------
__device__ __forceinline__ void mma_bf16(float c[4],
                                         unsigned a0, unsigned a1, unsigned a2, unsigned a3,
                                         unsigned b0, unsigned b1) {
    asm volatile(
        "mma.sync.aligned.m16n8k16.row.col.f32.bf16.bf16.f32 "
        "{%0,%1,%2,%3}, {%4,%5,%6,%7}, {%8,%9}, {%0,%1,%2,%3};\n"
        : "+f"(c[0]), "+f"(c[1]), "+f"(c[2]), "+f"(c[3])
        : "r"(a0), "r"(a1), "r"(a2), "r"(a3), "r"(b0), "r"(b1));
}

__device__ __forceinline__ unsigned pack_bf2(__nv_bfloat16 a, __nv_bfloat16 b) {
    return (unsigned)__bfloat16_as_ushort(a) |
           ((unsigned)__bfloat16_as_ushort(b) << 16);
}

__global__ __launch_bounds__(128, 1)
void flash_kernel(const int* __restrict__ adj, float* __restrict__ out) {
    extern __shared__ __align__(16) unsigned char dynsmem[];
    __nv_bfloat16* sKh = (__nv_bfloat16*)dynsmem;            // [64][72]
    __nv_bfloat16* sKl = sKh + BN * 72;
    __nv_bfloat16* sVh = sKl + BN * 72;                       // [128][72]
    __nv_bfloat16* sVl = sVh + OUT_F * 72;

    const int tid  = threadIdx.x;
    const int warp = tid >> 5;
    const int lane = tid & 31;
    const int lr   = lane >> 2;   // group id (row within 8)
    const int qi   = lane & 3;    // thread-in-group

    const int mr   = blockIdx.x * BM + warp * 16;
    const int row0 = mr + lr;
    const int row1 = row0 + 8;

    // ---- Q fragments (hi/lo), 4 k-tiles of 16 -----------------------
    const unsigned* qh32 = (const unsigned*)g_Qh;
    const unsigned* ql32 = (const unsigned*)g_Ql;
    unsigned qh[4][4], ql[4][4];
#pragma unroll
    for (int kt = 0; kt < 4; kt++) {
        int b0 = row0 * 32 + qi + 8 * kt;
        int b1 = row1 * 32 + qi + 8 * kt;
        qh[kt][0] = qh32[b0];     qh[kt][1] = qh32[b1];
        qh[kt][2] = qh32[b0 + 4]; qh[kt][3] = qh32[b1 + 4];
        ql[kt][0] = ql32[b0];     ql[kt][1] = ql32[b1];
        ql[kt][2] = ql32[b0 + 4]; ql[kt][3] = ql32[b1 + 4];
    }

    float O[16][4];
#pragma unroll
    for (int v = 0; v < 16; v++)
#pragma unroll
        for (int i = 0; i < 4; i++) O[v][i] = 0.f;
    float m0 = -1e30f, m1 = -1e30f, l0 = 0.f, l1 = 0.f;

    const int2*  adj2  = (const int2*)adj;
    const uint4* gKh4  = (const uint4*)g_Kh;
    const uint4* gKl4  = (const uint4*)g_Kl;
    const uint4* gVh4  = (const uint4*)g_Vth;
    const uint4* gVl4  = (const uint4*)g_Vtl;
    uint4* sKh4 = (uint4*)sKh;
    uint4* sKl4 = (uint4*)sKl;
    uint4* sVh4 = (uint4*)sVh;
    uint4* sVl4 = (uint4*)sVl;
    const unsigned* sKh32 = (const unsigned*)sKh;
    const unsigned* sKl32 = (const unsigned*)sKl;
    const unsigned* sVh32 = (const unsigned*)sVh;
    const unsigned* sVl32 = (const unsigned*)sVl;

    for (int j0 = 0; j0 < N_NODES; j0 += BN) {
        // ---- prefetch adj (each quad covers one full 32B sector) ----
        int2 adjA[8], adjB[8];
#pragma unroll
        for (int nt = 0; nt < 8; nt++) {
            adjA[nt] = adj2[row0 * 4096 + (j0 >> 1) + 4 * nt + qi];
            adjB[nt] = adj2[row1 * 4096 + (j0 >> 1) + 4 * nt + qi];
        }

        // ---- fill K / Vt smem tiles (coalesced uint4) ---------------
#pragma unroll
        for (int i = tid; i < 512; i += 128) {
            int r = i >> 3, cw = i & 7;
            sKh4[r * KSTR4 + cw] = gKh4[(j0 + r) * 8 + cw];
            sKl4[r * KSTR4 + cw] = gKl4[(j0 + r) * 8 + cw];
        }
#pragma unroll
        for (int i = tid; i < 1024; i += 128) {
            int cl = i >> 3, kw = i & 7;
            sVh4[cl * KSTR4 + kw] = gVh4[cl * 1024 + (j0 >> 3) + kw];
            sVl4[cl * KSTR4 + kw] = gVl4[cl * 1024 + (j0 >> 3) + kw];
        }
        __syncthreads();

        // ---- S = Q K^T (3-term bf16 split -> ~fp32 accuracy) --------
        float S[8][4];
#pragma unroll
        for (int nt = 0; nt < 8; nt++) {
            S[nt][0] = S[nt][1] = S[nt][2] = S[nt][3] = 0.f;
#pragma unroll
            for (int kt = 0; kt < 4; kt++) {
                int bi = (8 * nt + lr) * KSTRW + qi + 8 * kt;
                unsigned bh0 = sKh32[bi], bh1 = sKh32[bi + 4];
                unsigned bl0 = sKl32[bi], bl1 = sKl32[bi + 4];
                mma_bf16(S[nt], qh[kt][0], qh[kt][1], qh[kt][2], qh[kt][3], bh0, bh1);
                mma_bf16(S[nt], ql[kt][0], ql[kt][1], ql[kt][2], ql[kt][3], bh0, bh1);
                mma_bf16(S[nt], qh[kt][0], qh[kt][1], qh[kt][2], qh[kt][3], bl0, bl1);
            }
        }

        // ---- mask + row max -----------------------------------------
        float rmax0 = -1e30f, rmax1 = -1e30f;
#pragma unroll
        for (int nt = 0; nt < 8; nt++) {
            if (adjA[nt].x <= 0) S[nt][0] = -1e30f;
            if (adjA[nt].y <= 0) S[nt][1] = -1e30f;
            if (adjB[nt].x <= 0) S[nt][2] = -1e30f;
            if (adjB[nt].y <= 0) S[nt][3] = -1e30f;
            rmax0 = fmaxf(rmax0, fmaxf(S[nt][0], S[nt][1]));
            rmax1 = fmaxf(rmax1, fmaxf(S[nt][2], S[nt][3]));
        }
        rmax0 = fmaxf(rmax0, __shfl_xor_sync(0xffffffffu, rmax0, 1));
        rmax0 = fmaxf(rmax0, __shfl_xor_sync(0xffffffffu, rmax0, 2));
        rmax1 = fmaxf(rmax1, __shfl_xor_sync(0xffffffffu, rmax1, 1));
        rmax1 = fmaxf(rmax1, __shfl_xor_sync(0xffffffffu, rmax1, 2));

        float mn0 = fmaxf(m0, rmax0), mn1 = fmaxf(m1, rmax1);
        float sc0 = __expf(m0 - mn0), sc1 = __expf(m1 - mn1);
        m0 = mn0; m1 = mn1;

        // ---- exp + pack P into bf16 hi/lo A-fragments ---------------
        float rs0 = 0.f, rs1 = 0.f;
        unsigned aph[4][4], apl[4][4];
#pragma unroll
        for (int kt2 = 0; kt2 < 4; kt2++) {
#pragma unroll
            for (int half = 0; half < 2; half++) {
                int nt = 2 * kt2 + half;
                float p0 = (S[nt][0] > -1e29f) ? __expf(S[nt][0] - mn0) : 0.f;
                float p1 = (S[nt][1] > -1e29f) ? __expf(S[nt][1] - mn0) : 0.f;
                float p2 = (S[nt][2] > -1e29f) ? __expf(S[nt][2] - mn1) : 0.f;
                float p3 = (S[nt][3] > -1e29f) ? __expf(S[nt][3] - mn1) : 0.f;
                rs0 += p0 + p1;
                rs1 += p2 + p3;
                __nv_bfloat16 h0 = __float2bfloat16(p0), h1 = __float2bfloat16(p1);
                __nv_bfloat16 h2 = __float2bfloat16(p2), h3 = __float2bfloat16(p3);
                __nv_bfloat16 e0 = __float2bfloat16(p0 - __bfloat162float(h0));
                __nv_bfloat16 e1 = __float2bfloat16(p1 - __bfloat162float(h1));
                __nv_bfloat16 e2 = __float2bfloat16(p2 - __bfloat162float(h2));
                __nv_bfloat16 e3 = __float2bfloat16(p3 - __bfloat162float(h3));
                aph[kt2][2 * half + 0] = pack_bf2(h0, h1);  // row g,  k lo/hi half
                aph[kt2][2 * half + 1] = pack_bf2(h2, h3);  // row g+8
                apl[kt2][2 * half + 0] = pack_bf2(e0, e1);
                apl[kt2][2 * half + 1] = pack_bf2(e2, e3);
            }
            // fix A-frag register order: {a0,a1,a2,a3} = {g/lo, g+8/lo, g/hi, g+8/hi}
        }
        // reorder halves into proper a0..a3 (half0 -> a0,a1 ; half1 -> a2,a3)
        // (written directly above: index 0,1 = half0, index 2,3 = half1) -- correct.

        rs0 += __shfl_xor_sync(0xffffffffu, rs0, 1);
        rs0 += __shfl_xor_sync(0xffffffffu, rs0, 2);
        rs1 += __shfl_xor_sync(0xffffffffu, rs1, 1);
        rs1 += __shfl_xor_sync(0xffffffffu, rs1, 2);
        l0 = l0 * sc0 + rs0;
        l1 = l1 * sc1 + rs1;

        // ---- rescale O ----------------------------------------------
#pragma unroll
        for (int v = 0; v < 16; v++) {
            O[v][0] *= sc0; O[v][1] *= sc0;
            O[v][2] *= sc1; O[v][3] *= sc1;
        }

        // ---- O += P V (3-term split) --------------------------------
#pragma unroll
        for (int vn = 0; vn < 16; vn++) {
#pragma unroll
            for (int kt2 = 0; kt2 < 4; kt2++) {
                int bi = (8 * vn + lr) * KSTRW + qi + 8 * kt2;
                unsigned vh0 = sVh32[bi], vh1 = sVh32[bi + 4];
                unsigned vl0 = sVl32[bi], vl1 = sVl32[bi + 4];
                mma_bf16(O[vn], aph[kt2][0], aph[kt2][1], aph[kt2][2], aph[kt2][3], vh0, vh1);
                mma_bf16(O[vn], apl[kt2][0], apl[kt2][1], apl[kt2][2], apl[kt2][3], vh0, vh1);
                mma_bf16(O[vn], aph[kt2][0], aph[kt2][1], aph[kt2][2], aph[kt2][3], vl0, vl1);
            }
        }
        __syncthreads();  // protect smem before next fill
    }

    // ---- finalize --------------------------------------------------
    float inv0 = 1.f / l0;
    float inv1 = 1.f / l1;
#pragma unroll
    for (int vn = 0; vn < 16; vn++) {
        int col = 8 * vn + 2 * qi;
        *(float2*)&out[row0 * OUT_F + col] = make_float2(O[vn][0] * inv0, O[vn][1] * inv0);
        *(float2*)&out[row1 * OUT_F + col] = make_float2(O[vn][2] * inv1, O[vn][3] * inv1);
    }
}

// ---------------- launch --------------------------------------------------
extern "C" void kernel_launch(void* const* d_in, const int* in_sizes, int n_in,
                              void* d_out, int out_size) {
    const float* h   = (const float*)d_in[0];
    const int*   adj = (const int*)d_in[1];
    const float* Ws  = (const float*)d_in[2];
    const float* Wt  = (const float*)d_in[3];
    const float* Wc  = (const float*)d_in[4];
    float* out = (float*)d_out;

    prep_kernel<<<N_NODES / 16, 256>>>(h, Ws, Wt, Wc);

    const int smem_bytes = (2 * BN * 72 + 2 * OUT_F * 72) * (int)sizeof(__nv_bfloat16);
    cudaFuncSetAttribute(flash_kernel,
                         cudaFuncAttributeMaxDynamicSharedMemorySize, smem_bytes);
    flash_kernel<<<N_NODES / BM, 128, smem_bytes>>>(adj, out);
}

// round 3
// speedup vs baseline: 1.5275x; 1.5275x over previous
#include <cuda_runtime.h>
#include <cuda_bf16.h>

#define N_NODES 8192
#define IN_F    128
#define HID     64
#define OUT_F   128
#define BM      64
#define BN      64
#define NITER   64          // per CTA after j-split (4096 / BN)

// K-row stride in smem: 64 data bf16 + 8 pad = 72 bf16 = 36 words = 9 uint4.
// Bank check (LDS.32): word addr = 36*n + j, lanes n=lr(0..7), j=qi(0..3)
//  -> bank = (4n + j) mod 32 : all 32 distinct -> conflict-free.
#define KSTRW 36
#define KSTR4 9
// uint4 sizes per buffer: Kh 576, Kl 576, Vh 1152, Vl 1152 -> 3456 u4 = 55296 B
#define BUF_U4 3456

// ---------------- scratch (static device globals; no allocs allowed) -----
__device__ __align__(16) __nv_bfloat16 g_Qh[N_NODES * HID];
__device__ __align__(16) __nv_bfloat16 g_Ql[N_NODES * HID];
__device__ __align__(16) __nv_bfloat16 g_Kh[N_NODES * HID];
__device__ __align__(16) __nv_bfloat16 g_Kl[N_NODES * HID];
// V stored TRANSPOSED: [OUT_F][N_NODES] so flash-kernel smem fills are coalesced
__device__ __align__(16) __nv_bfloat16 g_Vth[OUT_F * N_NODES];
__device__ __align__(16) __nv_bfloat16 g_Vtl[OUT_F * N_NODES];
// split-j partials
__device__ __align__(16) float g_Op[2][N_NODES][OUT_F];
__device__ float g_pm[2][N_NODES];
__device__ float g_pl[2][N_NODES];

// ---------------- cp.async helpers ---------------------------------------
__device__ __forceinline__ void cp16(void* s, const void* g) {
    unsigned sa = (unsigned)__cvta_generic_to_shared(s);
    asm volatile("cp.async.cg.shared.global [%0], [%1], 16;\n" :: "r"(sa), "l"(g));
}
__device__ __forceinline__ void cp_commit() {
    asm volatile("cp.async.commit_group;\n");
}
template <int N>
__device__ __forceinline__ void cp_wait() {
    asm volatile("cp.async.wait_group %0;\n" :: "n"(N));
}

// ---------------- prep: Whs/Wht/Whc + bf16 hi/lo splits ------------------
// grid 1024 blocks x 64 threads; block = 8 rows of h; thread = 4 cols of
// the concatenated [Ws|Wt|Wc] (256 cols total).
__global__ __launch_bounds__(64)
void prep_kernel(const float* __restrict__ h,
                 const float* __restrict__ Ws,
                 const float* __restrict__ Wt,
                 const float* __restrict__ Wc) {
    __shared__ float hs[8][128];
    const int row0 = blockIdx.x * 8;
    const int tid  = threadIdx.x;

    // fill hs: 8*32 float4 = 256 loads / 64 threads
    const float4* h4 = (const float4*)(h + row0 * IN_F);
#pragma unroll
    for (int i = tid; i < 256; i += 64) {
        float4 v = h4[i];
        *(float4*)&hs[i >> 5][(i & 31) * 4] = v;
    }
    __syncthreads();

    const int g = 4 * tid;            // global concat col
    const float* W;
    int stride, c;
    if (g < 64)       { W = Ws; stride = 64;  c = g; }
    else if (g < 128) { W = Wt; stride = 64;  c = g - 64; }
    else              { W = Wc; stride = 128; c = g - 128; }

    float acc[8][4];
#pragma unroll
    for (int r = 0; r < 8; r++)
#pragma unroll
        for (int j = 0; j < 4; j++) acc[r][j] = 0.f;

#pragma unroll 4
    for (int k = 0; k < 128; k++) {
        float4 w = *(const float4*)&W[k * stride + c];
#pragma unroll
        for (int r = 0; r < 8; r++) {
            float hv = hs[r][k];       // broadcast across all 64 threads
            acc[r][0] += hv * w.x;
            acc[r][1] += hv * w.y;
            acc[r][2] += hv * w.z;
            acc[r][3] += hv * w.w;
        }
    }

    if (g < 128) {
        __nv_bfloat16* dh = (g < 64) ? g_Qh : g_Kh;
        __nv_bfloat16* dl = (g < 64) ? g_Ql : g_Kl;
#pragma unroll
        for (int r = 0; r < 8; r++) {
            union { __nv_bfloat16 b[4]; uint2 u; } ph, pl;
#pragma unroll
            for (int j = 0; j < 4; j++) {
                float v = acc[r][j];
                __nv_bfloat16 hi = __float2bfloat16(v);
                ph.b[j] = hi;
                pl.b[j] = __float2bfloat16(v - __bfloat162float(hi));
            }
            *(uint2*)&dh[(row0 + r) * HID + c] = ph.u;
            *(uint2*)&dl[(row0 + r) * HID + c] = pl.u;
        }
    } else {
#pragma unroll
        for (int j = 0; j < 4; j++) {
            union { __nv_bfloat16 b[8]; uint4 u; } ph, pl;
#pragma unroll
            for (int r = 0; r < 8; r++) {
                float v = acc[r][j];
                __nv_bfloat16 hi = __float2bfloat16(v);
                ph.b[r] = hi;
                pl.b[r] = __float2bfloat16(v - __bfloat162float(hi));
            }
            size_t base = (size_t)(c + j) * N_NODES + row0;  // 8 rows = 16B
            *(uint4*)(g_Vth + base) = ph.u;
            *(uint4*)(g_Vtl + base) = pl.u;
        }
    }
}

// ---------------- flash attention ----------------------------------------
__device__ __forceinline__ void mma_bf16(float c[4],
                                         unsigned a0, unsigned a1, unsigned a2, unsigned a3,
                                         unsigned b0, unsigned b1) {
    asm volatile(
        "mma.sync.aligned.m16n8k16.row.col.f32.bf16.bf16.f32 "
        "{%0,%1,%2,%3}, {%4,%5,%6,%7}, {%8,%9}, {%0,%1,%2,%3};\n"
        : "+f"(c[0]), "+f"(c[1]), "+f"(c[2]), "+f"(c[3])
        : "r"(a0), "r"(a1), "r"(a2), "r"(a3), "r"(b0), "r"(b1));
}

__device__ __forceinline__ unsigned pack_bf2(__nv_bfloat16 a, __nv_bfloat16 b) {
    return (unsigned)__bfloat16_as_ushort(a) |
           ((unsigned)__bfloat16_as_ushort(b) << 16);
}

// grid = 256 CTAs: m-tile = bx & 127, j-half = bx >> 7. 128 threads.
__global__ __launch_bounds__(128, 2)
void flash_kernel(const int* __restrict__ adj) {
    extern __shared__ __align__(16) unsigned char dynsmem[];
    uint4* base4 = (uint4*)dynsmem;

    const int tid  = threadIdx.x;
    const int warp = tid >> 5;
    const int lane = tid & 31;
    const int lr   = lane >> 2;   // group id (row within 8)
    const int qi   = lane & 3;    // thread-in-group

    const int mtile = blockIdx.x & 127;
    const int jhalf = blockIdx.x >> 7;
    const int jbase = jhalf * (N_NODES / 2);

    const int mr   = mtile * BM + warp * 16;
    const int row0 = mr + lr;
    const int row1 = row0 + 8;

    // ---- Q fragments (hi/lo), 4 k-tiles of 16 -----------------------
    const unsigned* qh32 = (const unsigned*)g_Qh;
    const unsigned* ql32 = (const unsigned*)g_Ql;
    unsigned qh[4][4], ql[4][4];
#pragma unroll
    for (int kt = 0; kt < 4; kt++) {
        int b0 = row0 * 32 + qi + 8 * kt;
        int b1 = row1 * 32 + qi + 8 * kt;
        qh[kt][0] = qh32[b0];     qh[kt][1] = qh32[b1];
        qh[kt][2] = qh32[b0 + 4]; qh[kt][3] = qh32[b1 + 4];
        ql[kt][0] = ql32[b0];     ql[kt][1] = ql32[b1];
        ql[kt][2] = ql32[b0 + 4]; ql[kt][3] = ql32[b1 + 4];
    }

    float O[16][4];
#pragma unroll
    for (int v = 0; v < 16; v++)
#pragma unroll
        for (int i = 0; i < 4; i++) O[v][i] = 0.f;
    float m0 = -1e30f, m1 = -1e30f, l0 = 0.f, l1 = 0.f;

    const int2*  adj2 = (const int2*)adj;
    const uint4* gKh4 = (const uint4*)g_Kh;
    const uint4* gKl4 = (const uint4*)g_Kl;
    const uint4* gVh4 = (const uint4*)g_Vth;
    const uint4* gVl4 = (const uint4*)g_Vtl;

    // ---- prologue: fill buffer 0 ------------------------------------
    {
        uint4* bKh = base4;
        uint4* bKl = base4 + 576;
        uint4* bVh = base4 + 1152;
        uint4* bVl = base4 + 2304;
#pragma unroll
        for (int i = tid; i < 512; i += 128) {
            int r = i >> 3, cw = i & 7;
            cp16(&bKh[r * KSTR4 + cw], &gKh4[(jbase + r) * 8 + cw]);
            cp16(&bKl[r * KSTR4 + cw], &gKl4[(jbase + r) * 8 + cw]);
        }
#pragma unroll
        for (int i = tid; i < 1024; i += 128) {
            int cl = i >> 3, kw = i & 7;
            cp16(&bVh[cl * KSTR4 + kw], &gVh4[cl * 1024 + (jbase >> 3) + kw]);
            cp16(&bVl[cl * KSTR4 + kw], &gVl4[cl * 1024 + (jbase >> 3) + kw]);
        }
        cp_commit();
    }

    int buf = 0;
    for (int it = 0; it < NITER; ++it) {
        const int j0 = jbase + it * BN;

        // ---- adj prefetch (each quad covers one full 32B sector) ----
        int2 adjA[8], adjB[8];
#pragma unroll
        for (int nt = 0; nt < 8; nt++) {
            adjA[nt] = __ldcs(&adj2[row0 * 4096 + (j0 >> 1) + 4 * nt + qi]);
            adjB[nt] = __ldcs(&adj2[row1 * 4096 + (j0 >> 1) + 4 * nt + qi]);
        }

        // ---- issue fill of next buffer ------------------------------
        if (it + 1 < NITER) {
            const int jn = j0 + BN;
            uint4* bKh = base4 + (buf ^ 1) * BUF_U4;
            uint4* bKl = bKh + 576;
            uint4* bVh = bKh + 1152;
            uint4* bVl = bKh + 2304;
#pragma unroll
            for (int i = tid; i < 512; i += 128) {
                int r = i >> 3, cw = i & 7;
                cp16(&bKh[r * KSTR4 + cw], &gKh4[(jn + r) * 8 + cw]);
                cp16(&bKl[r * KSTR4 + cw], &gKl4[(jn + r) * 8 + cw]);
            }
#pragma unroll
            for (int i = tid; i < 1024; i += 128) {
                int cl = i >> 3, kw = i & 7;
                cp16(&bVh[cl * KSTR4 + kw], &gVh4[cl * 1024 + (jn >> 3) + kw]);
                cp16(&bVl[cl * KSTR4 + kw], &gVl4[cl * 1024 + (jn >> 3) + kw]);
            }
            cp_commit();
            cp_wait<1>();   // current buffer's group is done
        } else {
            cp_wait<0>();
        }
        __syncthreads();

        const unsigned* sKh32 = (const unsigned*)(base4 + buf * BUF_U4);
        const unsigned* sKl32 = sKh32 + 576 * 4;
        const unsigned* sVh32 = sKh32 + 1152 * 4;
        const unsigned* sVl32 = sKh32 + 2304 * 4;

        // ---- S = Q K^T (3-term bf16 split -> ~fp32 accuracy) --------
        float S[8][4];
#pragma unroll
        for (int nt = 0; nt < 8; nt++) {
            S[nt][0] = S[nt][1] = S[nt][2] = S[nt][3] = 0.f;
#pragma unroll
            for (int kt = 0; kt < 4; kt++) {
                int bi = (8 * nt + lr) * KSTRW + qi + 8 * kt;
                unsigned bh0 = sKh32[bi], bh1 = sKh32[bi + 4];
                unsigned bl0 = sKl32[bi], bl1 = sKl32[bi + 4];
                mma_bf16(S[nt], qh[kt][0], qh[kt][1], qh[kt][2], qh[kt][3], bh0, bh1);
                mma_bf16(S[nt], ql[kt][0], ql[kt][1], ql[kt][2], ql[kt][3], bh0, bh1);
                mma_bf16(S[nt], qh[kt][0], qh[kt][1], qh[kt][2], qh[kt][3], bl0, bl1);
            }
        }

        // ---- mask + row max -----------------------------------------
        float rmax0 = -1e30f, rmax1 = -1e30f;
#pragma unroll
        for (int nt = 0; nt < 8; nt++) {
            if (adjA[nt].x <= 0) S[nt][0] = -1e30f;
            if (adjA[nt].y <= 0) S[nt][1] = -1e30f;
            if (adjB[nt].x <= 0) S[nt][2] = -1e30f;
            if (adjB[nt].y <= 0) S[nt][3] = -1e30f;
            rmax0 = fmaxf(rmax0, fmaxf(S[nt][0], S[nt][1]));
            rmax1 = fmaxf(rmax1, fmaxf(S[nt][2], S[nt][3]));
        }
        rmax0 = fmaxf(rmax0, __shfl_xor_sync(0xffffffffu, rmax0, 1));
        rmax0 = fmaxf(rmax0, __shfl_xor_sync(0xffffffffu, rmax0, 2));
        rmax1 = fmaxf(rmax1, __shfl_xor_sync(0xffffffffu, rmax1, 1));
        rmax1 = fmaxf(rmax1, __shfl_xor_sync(0xffffffffu, rmax1, 2));

        float mn0 = fmaxf(m0, rmax0), mn1 = fmaxf(m1, rmax1);
        float sc0 = __expf(m0 - mn0), sc1 = __expf(m1 - mn1);
        m0 = mn0; m1 = mn1;

        // ---- exp + pack P into bf16 hi/lo A-fragments ---------------
        float rs0 = 0.f, rs1 = 0.f;
        unsigned aph[4][4], apl[4][4];
#pragma unroll
        for (int kt2 = 0; kt2 < 4; kt2++) {
#pragma unroll
            for (int half = 0; half < 2; half++) {
                int nt = 2 * kt2 + half;
                float p0 = (S[nt][0] > -1e29f) ? __expf(S[nt][0] - mn0) : 0.f;
                float p1 = (S[nt][1] > -1e29f) ? __expf(S[nt][1] - mn0) : 0.f;
                float p2 = (S[nt][2] > -1e29f) ? __expf(S[nt][2] - mn1) : 0.f;
                float p3 = (S[nt][3] > -1e29f) ? __expf(S[nt][3] - mn1) : 0.f;
                rs0 += p0 + p1;
                rs1 += p2 + p3;
                __nv_bfloat16 h0 = __float2bfloat16(p0), h1 = __float2bfloat16(p1);
                __nv_bfloat16 h2 = __float2bfloat16(p2), h3 = __float2bfloat16(p3);
                __nv_bfloat16 e0 = __float2bfloat16(p0 - __bfloat162float(h0));
                __nv_bfloat16 e1 = __float2bfloat16(p1 - __bfloat162float(h1));
                __nv_bfloat16 e2 = __float2bfloat16(p2 - __bfloat162float(h2));
                __nv_bfloat16 e3 = __float2bfloat16(p3 - __bfloat162float(h3));
                aph[kt2][2 * half + 0] = pack_bf2(h0, h1);  // row g
                aph[kt2][2 * half + 1] = pack_bf2(h2, h3);  // row g+8
                apl[kt2][2 * half + 0] = pack_bf2(e0, e1);
                apl[kt2][2 * half + 1] = pack_bf2(e2, e3);
            }
        }

        rs0 += __shfl_xor_sync(0xffffffffu, rs0, 1);
        rs0 += __shfl_xor_sync(0xffffffffu, rs0, 2);
        rs1 += __shfl_xor_sync(0xffffffffu, rs1, 1);
        rs1 += __shfl_xor_sync(0xffffffffu, rs1, 2);
        l0 = l0 * sc0 + rs0;
        l1 = l1 * sc1 + rs1;

        // ---- rescale O ----------------------------------------------
#pragma unroll
        for (int v = 0; v < 16; v++) {
            O[v][0] *= sc0; O[v][1] *= sc0;
            O[v][2] *= sc1; O[v][3] *= sc1;
        }

        // ---- O += P V (3-term split) --------------------------------
#pragma unroll
        for (int vn = 0; vn < 16; vn++) {
#pragma unroll
            for (int kt2 = 0; kt2 < 4; kt2++) {
                int bi = (8 * vn + lr) * KSTRW + qi + 8 * kt2;
                unsigned vh0 = sVh32[bi], vh1 = sVh32[bi + 4];
                unsigned vl0 = sVl32[bi], vl1 = sVl32[bi + 4];
                mma_bf16(O[vn], aph[kt2][0], aph[kt2][1], aph[kt2][2], aph[kt2][3], vh0, vh1);
                mma_bf16(O[vn], apl[kt2][0], apl[kt2][1], apl[kt2][2], apl[kt2][3], vh0, vh1);
                mma_bf16(O[vn], aph[kt2][0], aph[kt2][1], aph[kt2][2], aph[kt2][3], vl0, vl1);
            }
        }
        __syncthreads();  // all warps done reading before this buffer is refilled
        buf ^= 1;
    }

    // ---- store partials (unnormalized) ------------------------------
    float* op = &g_Op[jhalf][0][0];
#pragma unroll
    for (int vn = 0; vn < 16; vn++) {
        int col = 8 * vn + 2 * qi;
        *(float2*)&op[row0 * OUT_F + col] = make_float2(O[vn][0], O[vn][1]);
        *(float2*)&op[row1 * OUT_F + col] = make_float2(O[vn][2], O[vn][3]);
    }
    if (qi == 0) {
        g_pm[jhalf][row0] = m0; g_pl[jhalf][row0] = l0;
        g_pm[jhalf][row1] = m1; g_pl[jhalf][row1] = l1;
    }
}

// ---------------- merge the two j-halves ----------------------------------
// grid 1024 x 256: block = 8 rows, thread = 4 cols
__global__ __launch_bounds__(256)
void merge_kernel(float* __restrict__ out) {
    const int row = blockIdx.x * 8 + (threadIdx.x >> 5);
    const int c   = (threadIdx.x & 31) * 4;

    float ma = g_pm[0][row], mb = g_pm[1][row];
    float la = g_pl[0][row], lb = g_pl[1][row];
    float M  = fmaxf(ma, mb);
    float sa = __expf(ma - M), sb = __expf(mb - M);
    float inv = 1.f / (la * sa + lb * sb);

    float4 a = *(const float4*)&g_Op[0][row][c];
    float4 b = *(const float4*)&g_Op[1][row][c];
    float4 r;
    r.x = (a.x * sa + b.x * sb) * inv;
    r.y = (a.y * sa + b.y * sb) * inv;
    r.z = (a.z * sa + b.z * sb) * inv;
    r.w = (a.w * sa + b.w * sb) * inv;
    *(float4*)&out[row * OUT_F + c] = r;
}

// ---------------- launch --------------------------------------------------
extern "C" void kernel_launch(void* const* d_in, const int* in_sizes, int n_in,
                              void* d_out, int out_size) {
    const float* h   = (const float*)d_in[0];
    const int*   adj = (const int*)d_in[1];
    const float* Ws  = (const float*)d_in[2];
    const float* Wt  = (const float*)d_in[3];
    const float* Wc  = (const float*)d_in[4];
    float* out = (float*)d_out;

    prep_kernel<<<N_NODES / 8, 64>>>(h, Ws, Wt, Wc);

    const int smem_bytes = 2 * BUF_U4 * 16;   // 110592 B
    cudaFuncSetAttribute(flash_kernel,
                         cudaFuncAttributeMaxDynamicSharedMemorySize, smem_bytes);
    flash_kernel<<<256, 128, smem_bytes>>>(adj);

    merge_kernel<<<N_NODES / 8, 256>>>(out);
}